// round 17
// baseline (speedup 1.0000x reference)
#include <cuda_runtime.h>
#include <cstdint>

#define BV     32
#define TT     2048
#define DD     512
#define MAXRUN 1024
#define GBLK   608                  // 152 SMs * 4
#define RCAP   64                   // max runs staged per block (ceil(32768/608)=54)
#define CTf    0.7f
#define CPTf   0.5f

// ---------------- device scratch (no allocations allowed) ----------------
__device__ float4   g_meta[BV * MAXRUN]; // {start, len, 1/cnt, 1/rep}, per-video compacted
__device__ unsigned g_mask[BV * MAXRUN]; // rep bitmask (first 32 rows of each qual run)
__device__ float    g_vid_attn[BV];
__device__ int      g_nqual[BV];
__device__ float    g_bsum[GBLK];
__device__ int      g_done;              // reset by last block each launch

// ============================================================================
// Kernel A: run analysis (unchanged — measured good).
// ============================================================================
__global__ __launch_bounds__(256) void runAnalysisKernel(const float* __restrict__ attn)
{
    __shared__ float         s_attn[TT];
    __shared__ unsigned char s_predB[258];
    __shared__ int           s_wTot[8];
    __shared__ int           s_total;
    __shared__ int           s_rstart[MAXRUN];
    __shared__ int           s_rend[MAXRUN];
    __shared__ int           s_wq[8];
    __shared__ float         s_red[8];

    const int b    = blockIdx.x;
    const int tid  = threadIdx.x;
    const int lane = tid & 31;
    const int warp = tid >> 5;
    const float* a_row = attn + (b << 11);

    const float4 v0 = ((const float4*)a_row)[tid * 2];
    const float4 v1 = ((const float4*)a_row)[tid * 2 + 1];
    ((float4*)s_attn)[tid * 2]     = v0;
    ((float4*)s_attn)[tid * 2 + 1] = v1;
    const float av[8] = {v0.x, v0.y, v0.z, v0.w, v1.x, v1.y, v1.z, v1.w};
    unsigned int pb = 0;
    #pragma unroll
    for (int j = 0; j < 8; j++) pb |= (av[j] > CPTf ? 1u : 0u) << j;
    s_predB[tid + 1] = (unsigned char)pb;
    if (tid == 0) { s_predB[0] = 0; s_predB[257] = 0; }
    __syncthreads();

    const unsigned prevB = s_predB[tid];
    const unsigned nextB = s_predB[tid + 2];
    const unsigned carry = (prevB >> 7) & 1u;
    const unsigned nxt   = (nextB & 1u) << 8;
    const unsigned ext   = pb | nxt;
    const unsigned stBits = pb & ~((pb << 1) | carry);
    const unsigned enBits = pb & ~(ext >> 1);

    int pref[8];
    int localTot = 0;
    #pragma unroll
    for (int j = 0; j < 8; j++) {
        localTot += (stBits >> j) & 1;
        pref[j] = localTot;
    }
    int incl = localTot;
    #pragma unroll
    for (int o = 1; o < 32; o <<= 1) {
        int u = __shfl_up_sync(0xffffffffu, incl, o);
        if (lane >= o) incl += u;
    }
    if (lane == 31) s_wTot[warp] = incl;
    __syncthreads();
    if (tid == 0) {
        int acc = 0;
        #pragma unroll
        for (int w = 0; w < 8; w++) { const int v = s_wTot[w]; s_wTot[w] = acc; acc += v; }
        s_total = acc;
    }
    __syncthreads();

    const int threadBase = s_wTot[warp] + (incl - localTot);
    const int base_t = tid * 8;
    #pragma unroll
    for (int j = 0; j < 8; j++) {
        const int rid = threadBase + pref[j] - 1;
        if ((stBits >> j) & 1) s_rstart[rid] = base_t + j;
        if ((enBits >> j) & 1) s_rend[rid]   = base_t + j;
    }
    __syncthreads();

    const int total = s_total;
    float attnAcc = 0.f;
    int      t0l[4], lenl[4];
    float    irl[4];
    unsigned mskl[4];
    int      q = 0;
    #pragma unroll
    for (int j = 0; j < 4; j++) {
        const int r = 4 * tid + j;
        t0l[j] = 0; lenl[j] = 0; irl[j] = 0.f; mskl[j] = 0u;
        if (r < total) {
            const int t0  = s_rstart[r];
            const int len = s_rend[r] - t0 + 1;
            float sum = 0.f; int rep = 0; unsigned mk = 0u;
            for (int l = 0; l < len; l++) {
                const float a = s_attn[t0 + l];
                sum += a;
                const int isrep = (a > CTf) ? 1 : 0;
                rep += isrep;
                if (l < 32) mk |= ((unsigned)isrep) << l;
            }
            const float mean = sum / (float)len;
            float ssq = 0.f;
            for (int l = 0; l < len; l++) {
                const float d = s_attn[t0 + l] - mean;
                ssq += d * d;
            }
            attnAcc += ssq / (float)len;
            t0l[j]  = t0;
            lenl[j] = len;
            irl[j]  = (rep > 0) ? (1.0f / (float)rep) : 0.0f;
            mskl[j] = mk;
            q += (rep > 0) ? 1 : 0;
        }
    }

    int qi = q;
    #pragma unroll
    for (int o = 1; o < 32; o <<= 1) {
        int u = __shfl_up_sync(0xffffffffu, qi, o);
        if (lane >= o) qi += u;
    }
    if (lane == 31) s_wq[warp] = qi;
    float ar = attnAcc;
    #pragma unroll
    for (int o = 16; o > 0; o >>= 1) ar += __shfl_xor_sync(0xffffffffu, ar, o);
    if (lane == 0) s_red[warp] = ar;
    __syncthreads();
    if (tid == 0) {
        int qa = 0; float asum = 0.f;
        #pragma unroll
        for (int w = 0; w < 8; w++) {
            const int tq = s_wq[w]; s_wq[w] = qa; qa += tq;
            asum += s_red[w];
        }
        g_vid_attn[b] = asum / (float)max(total, 1);
        g_nqual[b]    = qa;
    }
    __syncthreads();
    int slot = s_wq[warp] + (qi - q);
    #pragma unroll
    for (int j = 0; j < 4; j++) {
        if (irl[j] != 0.f) {
            float4 m;
            m.x = __int_as_float(t0l[j]);
            m.y = __int_as_float(lenl[j]);
            m.z = 1.0f / (float)lenl[j];
            m.w = irl[j];
            g_meta[(b << 10) + slot] = m;
            g_mask[(b << 10) + slot] = mskl[j];
            slot++;
        }
    }
}

// ============================================================================
// Kernel B: staged metadata (as R14); inner loop rebuilt BRANCH-FREE:
// x4 row unroll with clamped indices (min(j, L-1)) so all 8 LDG.128s issue
// unconditionally in one burst; out-of-range rows neutralized by coeff=0
// (FSEL, not a branch). Warp item = 2 units (run x quarter-D).
// ============================================================================
__global__ __launch_bounds__(256) void featKernel(const float* __restrict__ attn,
                                                  const float* __restrict__ feat,
                                                  float* __restrict__ out)
{
    __shared__ int      s_qbase[BV + 1];
    __shared__ float4   s_meta[RCAP];
    __shared__ unsigned s_mask[RCAP];
    __shared__ int      s_vid[RCAP];
    __shared__ float    s_part[8];
    __shared__ float    s_red[8];
    __shared__ int      s_isLast;

    const int tid  = threadIdx.x;
    const int lane = tid & 31;
    const int warp = tid >> 5;

    if (warp == 0) {                      // prefix of qual counts
        int nq = (lane < BV) ? g_nqual[lane] : 0;
        int sc = nq;
        #pragma unroll
        for (int o = 1; o < 32; o <<= 1) {
            int u = __shfl_up_sync(0xffffffffu, sc, o);
            if (lane >= o) sc += u;
        }
        if (lane < BV) s_qbase[lane + 1] = sc;
        if (lane == 0) s_qbase[0] = 0;
    }
    __syncthreads();
    const int Q      = s_qbase[BV];
    const int perBlk = (Q + (int)gridDim.x - 1) / (int)gridDim.x;
    const int r0     = blockIdx.x * perBlk;
    const int r1     = min(r0 + perBlk, Q);
    const int nr     = max(r1 - r0, 0);

    // ---- cooperative staging: one LDG round for all metas in range ----
    for (int i = tid; i < nr; i += 256) {
        const int g = r0 + i;
        int lo = 0, hi = BV;
        #pragma unroll
        for (int step = 0; step < 5; step++) {
            const int mid = (lo + hi) >> 1;
            if (s_qbase[mid] <= g) lo = mid; else hi = mid;
        }
        const int k = g - s_qbase[lo];
        s_meta[i] = __ldg(g_meta + (lo << 10) + k);
        s_mask[i] = __ldg(g_mask + (lo << 10) + k);
        s_vid[i]  = lo;
    }
    __syncthreads();

    // ---- units: (staged run, quarter). Warp processes 2 units at once. ----
    const int units = nr << 2;
    float ts = 0.f;

    for (int p = warp; (p << 1) < units; p += 8) {
        const int u0 = p << 1;
        const int u1 = u0 + 1;             // units is a multiple of 4
        const int i0 = u0 >> 2, q0 = u0 & 3;
        const int i1 = u1 >> 2, q1 = u1 & 3;

        const float4   mA = s_meta[i0];
        const float4   mB = s_meta[i1];
        const unsigned MA = s_mask[i0];
        const unsigned MB = s_mask[i1];
        const int      bA = s_vid[i0];
        const int      bB = s_vid[i1];

        const int sA = __float_as_int(mA.x), LA = __float_as_int(mA.y);
        const int sB = __float_as_int(mB.x), LB = __float_as_int(mB.y);
        const float cnA = mA.z, crA = mA.z - mA.w;
        const float cnB = mB.z, crB = mB.z - mB.w;

        const float4* fbA = (const float4*)feat + ((size_t)((bA << 11) + sA)) * 128
                          + (q0 << 5) + lane;
        const float4* fbB = (const float4*)feat + ((size_t)((bB << 11) + sB)) * 128
                          + (q1 << 5) + lane;

        float4 A = make_float4(0.f, 0.f, 0.f, 0.f);
        float4 B = A;

        const int limA = min(LA, 32), limB = min(LB, 32);
        const int lim  = max(limA, limB);

        for (int j = 0; j < lim; j += 4) {
            // clamped row indices: loads always execute (valid addresses)
            const int jA0 = min(j,     limA - 1), jA1 = min(j + 1, limA - 1);
            const int jA2 = min(j + 2, limA - 1), jA3 = min(j + 3, limA - 1);
            const int jB0 = min(j,     limB - 1), jB1 = min(j + 1, limB - 1);
            const int jB2 = min(j + 2, limB - 1), jB3 = min(j + 3, limB - 1);

            const float4 fA0 = __ldg(fbA + (size_t)jA0 * 128);
            const float4 fA1 = __ldg(fbA + (size_t)jA1 * 128);
            const float4 fA2 = __ldg(fbA + (size_t)jA2 * 128);
            const float4 fA3 = __ldg(fbA + (size_t)jA3 * 128);
            const float4 fB0 = __ldg(fbB + (size_t)jB0 * 128);
            const float4 fB1 = __ldg(fbB + (size_t)jB1 * 128);
            const float4 fB2 = __ldg(fbB + (size_t)jB2 * 128);
            const float4 fB3 = __ldg(fbB + (size_t)jB3 * 128);

            // coeff = in-range ? (rep ? crep : cnon) : 0   (selects, no branches)
            const float cA0 = (j     < limA) ? (((MA >> jA0) & 1u) ? crA : cnA) : 0.f;
            const float cA1 = (j + 1 < limA) ? (((MA >> jA1) & 1u) ? crA : cnA) : 0.f;
            const float cA2 = (j + 2 < limA) ? (((MA >> jA2) & 1u) ? crA : cnA) : 0.f;
            const float cA3 = (j + 3 < limA) ? (((MA >> jA3) & 1u) ? crA : cnA) : 0.f;
            const float cB0 = (j     < limB) ? (((MB >> jB0) & 1u) ? crB : cnB) : 0.f;
            const float cB1 = (j + 1 < limB) ? (((MB >> jB1) & 1u) ? crB : cnB) : 0.f;
            const float cB2 = (j + 2 < limB) ? (((MB >> jB2) & 1u) ? crB : cnB) : 0.f;
            const float cB3 = (j + 3 < limB) ? (((MB >> jB3) & 1u) ? crB : cnB) : 0.f;

            A.x += cA0*fA0.x + cA1*fA1.x + cA2*fA2.x + cA3*fA3.x;
            A.y += cA0*fA0.y + cA1*fA1.y + cA2*fA2.y + cA3*fA3.y;
            A.z += cA0*fA0.z + cA1*fA1.z + cA2*fA2.z + cA3*fA3.z;
            A.w += cA0*fA0.w + cA1*fA1.w + cA2*fA2.w + cA3*fA3.w;
            B.x += cB0*fB0.x + cB1*fB1.x + cB2*fB2.x + cB3*fB3.x;
            B.y += cB0*fB0.y + cB1*fB1.y + cB2*fB2.y + cB3*fB3.y;
            B.z += cB0*fB0.z + cB1*fB1.z + cB2*fB2.z + cB3*fB3.z;
            B.w += cB0*fB0.w + cB1*fB1.w + cB2*fB2.w + cB3*fB3.w;
        }

        // exactness tail for runs longer than 32 (uses attn directly)
        const int maxL = max(LA, LB);
        if (maxL > 32) {
            for (int j = 32; j < maxL; j++) {
                if (j < LA) {
                    const float a = __ldg(attn + (bA << 11) + sA + j);
                    const float4 f = __ldg(fbA + (size_t)j * 128);
                    const float c = (a > CTf) ? crA : cnA;
                    A.x += c*f.x; A.y += c*f.y; A.z += c*f.z; A.w += c*f.w;
                }
                if (j < LB) {
                    const float a = __ldg(attn + (bB << 11) + sB + j);
                    const float4 f = __ldg(fbB + (size_t)j * 128);
                    const float c = (a > CTf) ? crB : cnB;
                    B.x += c*f.x; B.y += c*f.y; B.z += c*f.z; B.w += c*f.w;
                }
            }
        }

        ts += A.x*A.x + A.y*A.y + A.z*A.z + A.w*A.w
            + B.x*B.x + B.y*B.y + B.z*B.z + B.w*B.w;
    }

    #pragma unroll
    for (int o = 16; o > 0; o >>= 1) ts += __shfl_xor_sync(0xffffffffu, ts, o);
    if (lane == 0) s_part[warp] = ts;
    __syncthreads();
    if (tid == 0) {
        float tot = 0.f;
        #pragma unroll
        for (int w = 0; w < 8; w++) tot += s_part[w];
        g_bsum[blockIdx.x] = tot;
        __threadfence();
        const int old = atomicAdd(&g_done, 1);
        s_isLast = (old == (int)gridDim.x - 1) ? 1 : 0;
    }
    __syncthreads();

    if (s_isLast) {
        __threadfence();
        float acc = 0.f;
        for (int i = tid; i < GBLK; i += 256) acc += g_bsum[i];
        #pragma unroll
        for (int o = 16; o > 0; o >>= 1) acc += __shfl_xor_sync(0xffffffffu, acc, o);
        if (lane == 0) s_red[warp] = acc;
        __syncthreads();
        if (tid == 0) {
            float f = 0.f;
            #pragma unroll
            for (int w = 0; w < 8; w++) f += s_red[w];
            float asum = 0.f; int qs = 0;
            #pragma unroll
            for (int v = 0; v < BV; v++) { asum += g_vid_attn[v]; qs += g_nqual[v]; }
            const float feat_loss = (f * (1.0f / (float)DD)) / (float)max(qs, 1);
            const float attn_loss = asum / (float)BV;
            out[0] = feat_loss + attn_loss;   // FW = AW = 1
            g_done = 0;                       // reset for next graph replay
        }
    }
}

// ============================================================================
extern "C" void kernel_launch(void* const* d_in, const int* in_sizes, int n_in,
                              void* d_out, int out_size)
{
    const float* attn = (const float*)d_in[0];
    const float* feat = (const float*)d_in[1];
    if (n_in >= 2 && in_sizes[0] > in_sizes[1]) {
        const float* tmp = attn; attn = feat; feat = tmp;
    }

    runAnalysisKernel<<<BV, 256>>>(attn);
    featKernel<<<GBLK, 256>>>(attn, feat, (float*)d_out);
}